// round 16
// baseline (speedup 1.0000x reference)
#include <cuda_runtime.h>
#include <cuda_bf16.h>
#include <math.h>

// Problem constants (fixed by reference)
#define B_      16
#define T_      8192
#define D_      512
#define H_      8
#define HD_     64
#define K_      4
#define TR_     8                 // rows per tile
#define TB_     (T_/TR_)          // 1024 tiles per batch
#define NTHR_   256
#define NBUF_   3

// One balanced wave at 3 CTAs/SM on 152 SMs: 456 = 8x29 + 8x28
#define G_      456
#define GB_HI_  29
#define GB_LO_  28
#define C_HI_   (8*GB_HI_)        // 232

// Per-warp buffer: 8 rows x 68 floats (64 data + 4 pad) + 8 mask ints.
#define WSTR_    68
#define WBUF_F   (TR_*WSTR_ + 8)          // 552 floats = 2208 B
#define SM_WARPS_F (H_*NBUF_*WBUF_F)      // 13248 floats
#define SM_P_F   (H_*TR_*K_)              // 256 floats
#define SMEM_BYTES ((SM_WARPS_F + SM_P_F)*4)   // 54016 B -> 3 CTAs/SM

// ---------------- device scratch (no allocations allowed) ----------------
__device__ __align__(16) float g_pool[B_*K_*D_];     // atomic accumulators
__device__ __align__(16) float g_lsum[B_*K_*H_];     // atomic denominators

// ---------------- packed fp32x2 FMA (Blackwell) ----------------
union F2U { float2 f; unsigned long long u; };
__device__ __forceinline__ float2 ffma2(float2 a, float2 b, float2 c) {
    F2U A, Bv, C, Dv;
    A.f = a; Bv.f = b; C.f = c;
    asm("fma.rn.f32x2 %0, %1, %2, %3;" : "=l"(Dv.u) : "l"(A.u), "l"(Bv.u), "l"(C.u));
    return Dv.f;
}

#define CP_COMMIT() asm volatile("cp.async.commit_group;")
#define CP_WAIT1()  asm volatile("cp.async.wait_group 1;")
#define CP_WAIT0()  asm volatile("cp.async.wait_group 0;")

__device__ __forceinline__ void cp16(float* dst_sh, const void* src) {
    unsigned d = (unsigned)__cvta_generic_to_shared(dst_sh);
    asm volatile("cp.async.cg.shared.global [%0], [%1], 16;" :: "r"(d), "l"(src));
}

// Per-warp: copy this head's 64-float slice of 8 rows (+ 8 mask ints).
__device__ __forceinline__ void issue_wtile(const float* __restrict__ src,
                                            float* __restrict__ dst,
                                            const int* __restrict__ msrc,
                                            int lane)
{
    #pragma unroll
    for (int i = 0; i < 4; i++) {
        int cchunk = lane + 32 * i;          // 0..127
        int row = cchunk >> 4;               // 0..7
        int ch  = cchunk & 15;               // 0..15
        cp16(dst + row * WSTR_ + ch * 4, src + (long)row * D_ + ch * 4);
    }
    if (lane < 2)
        cp16(dst + TR_ * WSTR_ + lane * 4, msrc + lane * 4);
}

// ======================================================================
// Kernel 1: warp-autonomous attention pooling, fixed softmax shift (m=0).
// lane = (half, r4, k): each lane covers 32 dims of one (row, query);
// halves combined with shfl_xor(16). q = 8 float4 = 32 regs ->
// 3 CTAs/SM (6 warps/SMSP). Two row-passes per 8-row tile.
// ======================================================================
__global__ void __launch_bounds__(NTHR_, 3)
attn_main(const float* __restrict__ x, const int* __restrict__ mask,
          const float* __restrict__ queries)
{
    extern __shared__ float sm[];
    float* p_sh = sm + SM_WARPS_F;             // [H][8][K]

    const int c    = blockIdx.x;
    const int tid  = threadIdx.x;
    const int w    = tid >> 5;                 // warp == head
    const int lane = tid & 31;
    const int half = lane >> 4;                // 0/1: which 32-dim half
    const int r4   = (lane >> 2) & 3;          // row within pass
    const int k_ln = lane & 3;                 // this lane's query index

    int b, j, Gb;
    if (c < C_HI_) { b = c / GB_HI_; j = c % GB_HI_; Gb = GB_HI_; }
    else { int c2 = c - C_HI_; b = 8 + c2 / GB_LO_; j = c2 % GB_LO_; Gb = GB_LO_; }
    const int tstart = (j * TB_) / Gb;
    const int ntiles = ((j + 1) * TB_) / Gb - tstart;   // ~35-36, always >= 3

    const float* xw = x + ((long)b * T_ + (long)tstart * TR_) * D_ + w * HD_;
    const int*   mw = mask + (long)b * T_ + tstart * TR_;
    float* wb  = sm + w * NBUF_ * WBUF_F;      // private buffers
    float* p_w = p_sh + w * TR_ * K_;

    // ---- q -> registers: this lane's query row, 32 dims of this head ----
    float4 q[8];
    const float4* qsrc = reinterpret_cast<const float4*>(
                             queries + (long)k_ln * D_ + w * HD_ + half * 32);
    #pragma unroll
    for (int i = 0; i < 8; i++) q[i] = __ldg(qsrc + i);

    float  l = 0.f;
    float2 acc[K_];
    #pragma unroll
    for (int k = 0; k < K_; k++) acc[k] = make_float2(0.f, 0.f);

    // prologue: 2 tiles in flight
    issue_wtile(xw, wb, mw, lane);
    CP_COMMIT();
    issue_wtile(xw + (long)TR_ * D_, wb + WBUF_F, mw + TR_, lane);
    CP_COMMIT();

    const int hshift = half * 4;               // bank-disjoint chunk phase

    for (int tl = 0; tl < ntiles; tl++) {
        if (tl + 1 < ntiles) CP_WAIT1(); else CP_WAIT0();
        __syncwarp();

        float* tile = wb + (tl % NBUF_) * WBUF_F;
        const int* msk = (const int*)(tile + TR_ * WSTR_);

        // ---- phase 1: two passes of 4 rows; 32-dim half-dots ----
        #pragma unroll
        for (int pass = 0; pass < 2; pass++) {
            const int row = pass * 4 + r4;
            const float* vrow = tile + row * WSTR_ + half * 32;
            float2 s0 = make_float2(0.f, 0.f), s1 = make_float2(0.f, 0.f);
            #pragma unroll
            for (int jj = 0; jj < 8; jj += 2) {
                int c0 = (jj + hshift) & 7;
                int c1 = (jj + 1 + hshift) & 7;
                float4 va = *reinterpret_cast<const float4*>(vrow + c0 * 4);
                float4 vb = *reinterpret_cast<const float4*>(vrow + c1 * 4);
                s0 = ffma2(make_float2(va.x, va.y), make_float2(q[c0].x, q[c0].y), s0);
                s1 = ffma2(make_float2(va.z, va.w), make_float2(q[c0].z, q[c0].w), s1);
                s0 = ffma2(make_float2(vb.x, vb.y), make_float2(q[c1].x, q[c1].y), s0);
                s1 = ffma2(make_float2(vb.z, vb.w), make_float2(q[c1].z, q[c1].w), s1);
            }
            float v = (s0.x + s1.x) + (s0.y + s1.y);
            v += __shfl_xor_sync(0xffffffffu, v, 16);   // combine halves
            float p = (msk[row] == 0) ? 0.f : __expf(v * 0.125f);
            l += p;                                      // both halves count
            if (half == 0) p_w[row * K_ + k_ln] = p;
        }
        __syncwarp();

        // ---- phase 2: lane owns d = {2*lane, 2*lane+1} of this head ----
        const float* base2 = tile + 2 * lane;
        #pragma unroll
        for (int t = 0; t < TR_; t++) {
            float2 v2 = *reinterpret_cast<const float2*>(base2 + t * WSTR_);
            float4 p4 = *reinterpret_cast<const float4*>(p_w + t * K_);
            acc[0] = ffma2(v2, make_float2(p4.x, p4.x), acc[0]);
            acc[1] = ffma2(v2, make_float2(p4.y, p4.y), acc[1]);
            acc[2] = ffma2(v2, make_float2(p4.z, p4.z), acc[2]);
            acc[3] = ffma2(v2, make_float2(p4.w, p4.w), acc[3]);
        }
        __syncwarp();                          // lanes done reading buffer & p_w

        if (tl + 2 < ntiles) {
            issue_wtile(xw + (long)(tl + 2) * TR_ * D_,
                        wb + ((tl + 2) % NBUF_) * WBUF_F,
                        mw + (tl + 2) * TR_, lane);
            CP_COMMIT();
        }
    }

    // ---- reduce l: lanes sharing k are {k + 4*r4 + 16*half}; each task
    // counted twice (both halves) -> xor 4,8,16 then * 0.5 ----
    l += __shfl_xor_sync(0xffffffffu, l, 4);
    l += __shfl_xor_sync(0xffffffffu, l, 8);
    l += __shfl_xor_sync(0xffffffffu, l, 16);
    l *= 0.5f;

    // ---- atomic tail: plain sums across CTAs (m = 0 everywhere) ----
    if (lane < K_)
        atomicAdd(&g_lsum[((long)b * K_ + lane) * H_ + w], l);
    #pragma unroll
    for (int k = 0; k < K_; k++) {
        float* dst = &g_pool[((long)b * K_ + k) * D_ + w * HD_ + 2 * lane];
        atomicAdd(dst,     acc[k].x);
        atomicAdd(dst + 1, acc[k].y);
    }
}

// ======================================================================
// Kernel 2 (R15): normalize + linear projection, warp-per-(row-pair, 8 j).
// ======================================================================
__global__ void __launch_bounds__(256)
epi_k(const float* __restrict__ w_out, const float* __restrict__ b_out,
      float* __restrict__ out)
{
    const int gw   = blockIdx.x * 8 + (threadIdx.x >> 5);   // 0..2047
    const int lane = threadIdx.x & 31;
    const int jg   = gw >> 5;               // 0..63
    const int rp   = gw & 31;               // row pair: rows 2rp, 2rp+1
    const int r0   = rp * 2, r1 = rp * 2 + 1;

    const float4* pr0 = reinterpret_cast<const float4*>(g_pool + (long)r0 * D_);
    const float4* pr1 = reinterpret_cast<const float4*>(g_pool + (long)r1 * D_);
    float4 pv0[4], pv1[4];
    #pragma unroll
    for (int i = 0; i < 4; i++) {
        int idx = i * 32 + lane;             // float4 index; dim = idx*4
        int h   = idx >> 4;
        float inv0 = 1.f / g_lsum[r0 * H_ + h];
        float inv1 = 1.f / g_lsum[r1 * H_ + h];
        float4 v0 = pr0[idx];
        float4 v1 = pr1[idx];
        pv0[i] = make_float4(v0.x*inv0, v0.y*inv0, v0.z*inv0, v0.w*inv0);
        pv1[i] = make_float4(v1.x*inv1, v1.y*inv1, v1.z*inv1, v1.w*inv1);
    }

    float my0 = 0.f, my1 = 0.f;
    #pragma unroll
    for (int j0 = 0; j0 < 8; j0++) {
        const float4* wr = reinterpret_cast<const float4*>(
                               w_out + (long)(jg * 8 + j0) * D_);
        float2 sA = make_float2(0.f, 0.f), sB = make_float2(0.f, 0.f);
        #pragma unroll
        for (int i = 0; i < 4; i++) {
            float4 wv = wr[i * 32 + lane];
            sA = ffma2(make_float2(wv.x, wv.y), make_float2(pv0[i].x, pv0[i].y), sA);
            sA = ffma2(make_float2(wv.z, wv.w), make_float2(pv0[i].z, pv0[i].w), sA);
            sB = ffma2(make_float2(wv.x, wv.y), make_float2(pv1[i].x, pv1[i].y), sB);
            sB = ffma2(make_float2(wv.z, wv.w), make_float2(pv1[i].z, pv1[i].w), sB);
        }
        float tA = sA.x + sA.y, tB = sB.x + sB.y;
        #pragma unroll
        for (int off = 16; off > 0; off >>= 1) {
            tA += __shfl_xor_sync(0xffffffffu, tA, off);
            tB += __shfl_xor_sync(0xffffffffu, tB, off);
        }
        if (lane == j0) { my0 = tA; my1 = tB; }
    }

    if (lane < 8) {
        int j = jg * 8 + lane;
        float bj = b_out[j];
        out[(long)r0 * D_ + j] = bj + my0;
        out[(long)r1 * D_ + j] = bj + my1;
    }
}

// ======================================================================
extern "C" void kernel_launch(void* const* d_in, const int* in_sizes, int n_in,
                              void* d_out, int out_size)
{
    const float* x       = (const float*)d_in[0];
    const int*   mask    = (const int*)  d_in[1];
    const float* queries = (const float*)d_in[2];
    const float* w_out   = (const float*)d_in[3];
    const float* b_out   = (const float*)d_in[4];
    float* out = (float*)d_out;

    cudaFuncSetAttribute((const void*)attn_main,
                         cudaFuncAttributeMaxDynamicSharedMemorySize, SMEM_BYTES);

    // zero the atomic accumulators via graph memset nodes
    void* p_pool = nullptr; void* p_lsum = nullptr;
    cudaGetSymbolAddress(&p_pool, g_pool);
    cudaGetSymbolAddress(&p_lsum, g_lsum);
    cudaMemsetAsync(p_pool, 0, sizeof(float) * B_ * K_ * D_);
    cudaMemsetAsync(p_lsum, 0, sizeof(float) * B_ * K_ * H_);

    attn_main<<<G_, NTHR_, SMEM_BYTES>>>(x, mask, queries);
    epi_k<<<256, 256>>>(w_out, b_out, out);
}

// round 17
// speedup vs baseline: 1.2601x; 1.2601x over previous
#include <cuda_runtime.h>
#include <cuda_bf16.h>
#include <math.h>

// Problem constants (fixed by reference)
#define B_      16
#define T_      8192
#define D_      512
#define H_      8
#define HD_     64
#define K_      4
#define TR_     8                 // rows per tile
#define TB_     (T_/TR_)          // 1024 tiles per batch
#define NTHR_   256
#define NBUF_   4

// One balanced wave at 2 CTAs/SM on 152 SMs: 304 = 16 x 19
#define GB_     19
#define G_      (B_*GB_)

// Per-warp buffer: 8 rows x 68 floats (64 data + 4 pad) + 8 mask ints.
#define WSTR_    68                       // 272 B row pitch (16B-aligned)
#define WBUF_F   (TR_*WSTR_ + 8)          // 552 floats = 2208 B (16B-aligned)
#define SM_WARPS_F (H_*NBUF_*WBUF_F)      // 17664 floats
#define SM_P_F   (H_*TR_*K_)              // 256 floats
#define SM_MBAR_B (H_*NBUF_*8)            // 256 bytes of mbarriers
#define SMEM_BYTES ((SM_WARPS_F + SM_P_F)*4 + SM_MBAR_B)   // 71936 B
#define TILE_TX  (TR_*256 + 32)           // 2080 bytes per tile

// ---------------- device scratch (no allocations allowed) ----------------
__device__ __align__(16) float g_pool[B_*K_*D_];     // atomic accumulators
__device__ __align__(16) float g_lsum[B_*K_*H_];     // atomic denominators

// ---------------- packed fp32x2 FMA (Blackwell) ----------------
union F2U { float2 f; unsigned long long u; };
__device__ __forceinline__ float2 ffma2(float2 a, float2 b, float2 c) {
    F2U A, Bv, C, Dv;
    A.f = a; Bv.f = b; C.f = c;
    asm("fma.rn.f32x2 %0, %1, %2, %3;" : "=l"(Dv.u) : "l"(A.u), "l"(Bv.u), "l"(C.u));
    return Dv.f;
}

// ---------------- cp.async.bulk + mbarrier primitives ----------------
__device__ __forceinline__ void mbar_init(unsigned mbar, unsigned cnt) {
    asm volatile("mbarrier.init.shared.b64 [%0], %1;" :: "r"(mbar), "r"(cnt) : "memory");
}
__device__ __forceinline__ void mbar_expect_tx(unsigned mbar, unsigned bytes) {
    asm volatile("mbarrier.arrive.expect_tx.shared.b64 _, [%0], %1;"
                 :: "r"(mbar), "r"(bytes) : "memory");
}
__device__ __forceinline__ void bulk_g2s(unsigned dst, const void* src,
                                         unsigned bytes, unsigned mbar) {
    asm volatile(
        "cp.async.bulk.shared::cta.global.mbarrier::complete_tx::bytes [%0], [%1], %2, [%3];"
        :: "r"(dst), "l"(src), "r"(bytes), "r"(mbar) : "memory");
}
__device__ __forceinline__ void mbar_wait(unsigned mbar, unsigned parity) {
    asm volatile(
        "{\n\t"
        ".reg .pred P;\n"
        "W_%=:\n\t"
        "mbarrier.try_wait.parity.acquire.cta.shared::cta.b64 P, [%0], %1, 0x989680;\n\t"
        "@!P bra W_%=;\n\t"
        "}"
        :: "r"(mbar), "r"(parity) : "memory");
}

// Lane 0 only: one tile = 8 row-slices of 256B + 32B mask, one mbarrier.
__device__ __forceinline__ void issue_tile_bulk(const float* __restrict__ src,
                                                unsigned dst_u32,
                                                const int* __restrict__ msrc,
                                                unsigned mbar)
{
    mbar_expect_tx(mbar, TILE_TX);
    #pragma unroll
    for (int r = 0; r < TR_; r++)
        bulk_g2s(dst_u32 + r * (WSTR_*4), src + (long)r * D_, 256, mbar);
    bulk_g2s(dst_u32 + TR_ * (WSTR_*4), msrc, 32, mbar);
}

// ======================================================================
// Kernel 1: champion mainloop (R13) with cp.async.bulk tile loads.
// Warp-autonomous, fixed softmax shift (m=0), lane=(row,k), q in regs,
// NBUF=4, 3 tiles in flight via per-(warp,buffer) mbarriers.
// ======================================================================
__global__ void __launch_bounds__(NTHR_, 2)
attn_main(const float* __restrict__ x, const int* __restrict__ mask,
          const float* __restrict__ queries)
{
    extern __shared__ float sm[];
    float* p_sh = sm + SM_WARPS_F;             // [H][8][K]

    const unsigned sm_u32 = (unsigned)__cvta_generic_to_shared(sm);

    const int c    = blockIdx.x;
    const int tid  = threadIdx.x;
    const int w    = tid >> 5;                 // warp == head
    const int lane = tid & 31;
    const int row  = lane >> 2;                // 0..7
    const int k_ln = lane & 3;                 // this lane's query index

    const int b = c / GB_;
    const int j = c % GB_;
    const int tstart = (j * TB_) / GB_;
    const int ntiles = ((j + 1) * TB_) / GB_ - tstart;   // ~53-54, always >= 4

    const float* xw = x + ((long)b * T_ + (long)tstart * TR_) * D_ + w * HD_;
    const int*   mw = mask + (long)b * T_ + tstart * TR_;
    float* wb  = sm + w * NBUF_ * WBUF_F;      // private buffers (generic)
    const unsigned wb_u32   = sm_u32 + (unsigned)(w * NBUF_ * WBUF_F * 4);
    const unsigned mbar_u32 = sm_u32 + (unsigned)((SM_WARPS_F + SM_P_F) * 4
                                                  + w * NBUF_ * 8);
    float* p_w = p_sh + w * TR_ * K_;

    // ---- q -> registers: this lane's query row, this head's 64 dims ----
    float4 q[16];
    const float4* qsrc = reinterpret_cast<const float4*>(
                             queries + (long)k_ln * D_ + w * HD_);
    #pragma unroll
    for (int i = 0; i < 16; i++) q[i] = __ldg(qsrc + i);

    float  l = 0.f;
    float2 acc[K_];
    #pragma unroll
    for (int k = 0; k < K_; k++) acc[k] = make_float2(0.f, 0.f);

    // prologue: init this warp's 4 mbarriers, then 3 tiles in flight
    if (lane == 0) {
        #pragma unroll
        for (int i = 0; i < NBUF_; i++) mbar_init(mbar_u32 + i * 8, 1);
    }
    __syncwarp();
    if (lane == 0) {
        #pragma unroll
        for (int i = 0; i < 3; i++)
            issue_tile_bulk(xw + (long)i * TR_ * D_, wb_u32 + i * (WBUF_F*4),
                            mw + i * TR_, mbar_u32 + i * 8);
    }

    for (int tl = 0; tl < ntiles; tl++) {
        // wait for tile tl (buffer tl&3, parity flips every NBUF uses)
        mbar_wait(mbar_u32 + (tl & (NBUF_-1)) * 8, (tl >> 2) & 1);

        float* tile = wb + (tl & (NBUF_-1)) * WBUF_F;
        const int* msk = (const int*)(tile + TR_ * WSTR_);

        // ---- phase 1: 64-dim dot with 4 independent partial sums ----
        float2 s0 = make_float2(0.f, 0.f), s1 = make_float2(0.f, 0.f);
        float2 s2 = make_float2(0.f, 0.f), s3 = make_float2(0.f, 0.f);
        const float* vrow = tile + row * WSTR_;
        #pragma unroll
        for (int g = 0; g < 4; g++) {          // 4 groups of 4 float4 chunks
            float4 va = *reinterpret_cast<const float4*>(vrow + (g*4+0) * 4);
            float4 vb = *reinterpret_cast<const float4*>(vrow + (g*4+1) * 4);
            float4 vc = *reinterpret_cast<const float4*>(vrow + (g*4+2) * 4);
            float4 vd = *reinterpret_cast<const float4*>(vrow + (g*4+3) * 4);
            s0 = ffma2(make_float2(va.x, va.y), make_float2(q[g*4+0].x, q[g*4+0].y), s0);
            s1 = ffma2(make_float2(va.z, va.w), make_float2(q[g*4+0].z, q[g*4+0].w), s1);
            s2 = ffma2(make_float2(vb.x, vb.y), make_float2(q[g*4+1].x, q[g*4+1].y), s2);
            s3 = ffma2(make_float2(vb.z, vb.w), make_float2(q[g*4+1].z, q[g*4+1].w), s3);
            s0 = ffma2(make_float2(vc.x, vc.y), make_float2(q[g*4+2].x, q[g*4+2].y), s0);
            s1 = ffma2(make_float2(vc.z, vc.w), make_float2(q[g*4+2].z, q[g*4+2].w), s1);
            s2 = ffma2(make_float2(vd.x, vd.y), make_float2(q[g*4+3].x, q[g*4+3].y), s2);
            s3 = ffma2(make_float2(vd.z, vd.w), make_float2(q[g*4+3].z, q[g*4+3].w), s3);
        }
        float2 t01 = make_float2(s0.x + s1.x, s0.y + s1.y);
        float2 t23 = make_float2(s2.x + s3.x, s2.y + s3.y);
        float  v   = (t01.x + t23.x) + (t01.y + t23.y);
        float p = (msk[row] == 0) ? 0.f : __expf(v * 0.125f);
        l += p;
        p_w[lane] = p;                         // [row][k] contiguous, conflict-free
        __syncwarp();

        // ---- phase 2: lane owns d = {2*lane, 2*lane+1} of this head ----
        const float* base2 = tile + 2 * lane;
        #pragma unroll
        for (int t = 0; t < TR_; t++) {
            float2 v2 = *reinterpret_cast<const float2*>(base2 + t * WSTR_);
            float4 p4 = *reinterpret_cast<const float4*>(p_w + t * K_);
            acc[0] = ffma2(v2, make_float2(p4.x, p4.x), acc[0]);
            acc[1] = ffma2(v2, make_float2(p4.y, p4.y), acc[1]);
            acc[2] = ffma2(v2, make_float2(p4.z, p4.z), acc[2]);
            acc[3] = ffma2(v2, make_float2(p4.w, p4.w), acc[3]);
        }
        __syncwarp();                          // lanes done reading buffer & p_w

        if (tl + 3 < ntiles && lane == 0) {
            issue_tile_bulk(xw + (long)(tl + 3) * TR_ * D_,
                            wb_u32 + ((tl + 3) & (NBUF_-1)) * (WBUF_F*4),
                            mw + (tl + 3) * TR_,
                            mbar_u32 + ((tl + 3) & (NBUF_-1)) * 8);
        }
    }

    // ---- reduce l over rows (lanes sharing k = lane&3) ----
    l += __shfl_xor_sync(0xffffffffu, l, 4);
    l += __shfl_xor_sync(0xffffffffu, l, 8);
    l += __shfl_xor_sync(0xffffffffu, l, 16);

    // ---- atomic tail: plain sums across CTAs (m = 0 everywhere) ----
    if (lane < K_)
        atomicAdd(&g_lsum[((long)b * K_ + lane) * H_ + w], l);
    #pragma unroll
    for (int k = 0; k < K_; k++) {
        float* dst = &g_pool[((long)b * K_ + k) * D_ + w * HD_ + 2 * lane];
        atomicAdd(dst,     acc[k].x);
        atomicAdd(dst + 1, acc[k].y);
    }
}

// ======================================================================
// Kernel 2 (R15): normalize + linear projection, warp-per-(row-pair, 8 j).
// ======================================================================
__global__ void __launch_bounds__(256)
epi_k(const float* __restrict__ w_out, const float* __restrict__ b_out,
      float* __restrict__ out)
{
    const int gw   = blockIdx.x * 8 + (threadIdx.x >> 5);   // 0..2047
    const int lane = threadIdx.x & 31;
    const int jg   = gw >> 5;               // 0..63
    const int rp   = gw & 31;               // row pair: rows 2rp, 2rp+1
    const int r0   = rp * 2, r1 = rp * 2 + 1;

    const float4* pr0 = reinterpret_cast<const float4*>(g_pool + (long)r0 * D_);
    const float4* pr1 = reinterpret_cast<const float4*>(g_pool + (long)r1 * D_);
    float4 pv0[4], pv1[4];
    #pragma unroll
    for (int i = 0; i < 4; i++) {
        int idx = i * 32 + lane;             // float4 index; dim = idx*4
        int h   = idx >> 4;
        float inv0 = 1.f / g_lsum[r0 * H_ + h];
        float inv1 = 1.f / g_lsum[r1 * H_ + h];
        float4 v0 = pr0[idx];
        float4 v1 = pr1[idx];
        pv0[i] = make_float4(v0.x*inv0, v0.y*inv0, v0.z*inv0, v0.w*inv0);
        pv1[i] = make_float4(v1.x*inv1, v1.y*inv1, v1.z*inv1, v1.w*inv1);
    }

    float my0 = 0.f, my1 = 0.f;
    #pragma unroll
    for (int j0 = 0; j0 < 8; j0++) {
        const float4* wr = reinterpret_cast<const float4*>(
                               w_out + (long)(jg * 8 + j0) * D_);
        float2 sA = make_float2(0.f, 0.f), sB = make_float2(0.f, 0.f);
        #pragma unroll
        for (int i = 0; i < 4; i++) {
            float4 wv = wr[i * 32 + lane];
            sA = ffma2(make_float2(wv.x, wv.y), make_float2(pv0[i].x, pv0[i].y), sA);
            sA = ffma2(make_float2(wv.z, wv.w), make_float2(pv0[i].z, pv0[i].w), sA);
            sB = ffma2(make_float2(wv.x, wv.y), make_float2(pv1[i].x, pv1[i].y), sB);
            sB = ffma2(make_float2(wv.z, wv.w), make_float2(pv1[i].z, pv1[i].w), sB);
        }
        float tA = sA.x + sA.y, tB = sB.x + sB.y;
        #pragma unroll
        for (int off = 16; off > 0; off >>= 1) {
            tA += __shfl_xor_sync(0xffffffffu, tA, off);
            tB += __shfl_xor_sync(0xffffffffu, tB, off);
        }
        if (lane == j0) { my0 = tA; my1 = tB; }
    }

    if (lane < 8) {
        int j = jg * 8 + lane;
        float bj = b_out[j];
        out[(long)r0 * D_ + j] = bj + my0;
        out[(long)r1 * D_ + j] = bj + my1;
    }
}

// ======================================================================
extern "C" void kernel_launch(void* const* d_in, const int* in_sizes, int n_in,
                              void* d_out, int out_size)
{
    const float* x       = (const float*)d_in[0];
    const int*   mask    = (const int*)  d_in[1];
    const float* queries = (const float*)d_in[2];
    const float* w_out   = (const float*)d_in[3];
    const float* b_out   = (const float*)d_in[4];
    float* out = (float*)d_out;

    cudaFuncSetAttribute((const void*)attn_main,
                         cudaFuncAttributeMaxDynamicSharedMemorySize, SMEM_BYTES);

    // zero the atomic accumulators via graph memset nodes
    void* p_pool = nullptr; void* p_lsum = nullptr;
    cudaGetSymbolAddress(&p_pool, g_pool);
    cudaGetSymbolAddress(&p_lsum, g_lsum);
    cudaMemsetAsync(p_pool, 0, sizeof(float) * B_ * K_ * D_);
    cudaMemsetAsync(p_lsum, 0, sizeof(float) * B_ * K_ * H_);

    attn_main<<<G_, NTHR_, SMEM_BYTES>>>(x, mask, queries);
    epi_k<<<256, 256>>>(w_out, b_out, out);
}